// round 7
// baseline (speedup 1.0000x reference)
#include <cuda_runtime.h>
#include <cstdint>

#define L  384
#define D  128
#define H  128
#define LL (L * L)   // 147456

// Scratch — static device globals (no cudaMalloc allowed).
__device__ float g_LhT[(size_t)H * LL];   // [h][i*L+k]  (tf32-rounded)
__device__ float g_RhT[(size_t)H * LL];   // [h][j*L+k]  (tf32-rounded, j-major)
__device__ float g_updT[(size_t)H * LL];  // [h][i*L+j]  (tf32-rounded)
__device__ float g_Wo2[D * H];            // [d][h] = tf32(W_out[d][h]) (native order)

// ---------------------------------------------------------------------------
// helpers
// ---------------------------------------------------------------------------
__device__ __forceinline__ unsigned f2tf(float x) {
    unsigned r; asm("cvt.rna.tf32.f32 %0, %1;" : "=r"(r) : "f"(x)); return r;
}
__device__ __forceinline__ float f2tff(float x) { return __uint_as_float(f2tf(x)); }

__device__ __forceinline__ void mma8(float c[4], const unsigned a[4], const unsigned b[2]) {
    asm volatile(
        "mma.sync.aligned.m16n8k8.row.col.f32.tf32.tf32.f32 "
        "{%0,%1,%2,%3}, {%4,%5,%6,%7}, {%8,%9}, {%0,%1,%2,%3};"
        : "+f"(c[0]), "+f"(c[1]), "+f"(c[2]), "+f"(c[3])
        : "r"(a[0]), "r"(a[1]), "r"(a[2]), "r"(a[3]), "r"(b[0]), "r"(b[1]));
}

// ldmatrix.x4 on fp32 data viewed as b16 8x8 matrices (8x4 fp32 tiles).
__device__ __forceinline__ void ldsm4(unsigned r[4], const float* p) {
    unsigned a = (unsigned)__cvta_generic_to_shared(p);
    asm volatile("ldmatrix.sync.aligned.m8n8.x4.shared.b16 {%0,%1,%2,%3}, [%4];"
                 : "=r"(r[0]), "=r"(r[1]), "=r"(r[2]), "=r"(r[3]) : "r"(a));
}

__device__ __forceinline__ void cpa16(void* dst, const void* src) {
    unsigned sa = (unsigned)__cvta_generic_to_shared(dst);
    asm volatile("cp.async.cg.shared.global [%0], [%1], 16;" :: "r"(sa), "l"(src));
}
__device__ __forceinline__ void cpa_commit() { asm volatile("cp.async.commit_group;"); }
__device__ __forceinline__ void cpa_wait1()  { asm volatile("cp.async.wait_group 1;"); }

// ---------------------------------------------------------------------------
// Kernel 0: tf32-round W_out (native [d][h] order) -> g_Wo2
// ---------------------------------------------------------------------------
__global__ __launch_bounds__(256) void k_wt(const float* __restrict__ Wo) {
    int idx = blockIdx.x * 256 + threadIdx.x;   // 16384
    g_Wo2[idx] = f2tff(Wo[idx]);
}

// ---------------------------------------------------------------------------
// Kernel 1: projection GEMM (tf32 mma + ldmatrix).
//   isL: Lh(i, k=c, h) masked by mask[i*L+c]  -> g_LhT[h][i*L+c]
//   isR: Rh(k, j, h)   masked by mask[j*L+k]  -> g_RhT[h][j*L+k]  (j-major)
// Block 128 rows x 128 h. BK=16, 8 iters, reg-prefetch double buffer,
// tiles [m][k] / [n][k] pitch 20, 1 sync/iter.
// ---------------------------------------------------------------------------
#define P_STG 5120                    // floats: A 128*20 + B 128*20
#define PAS(s, m, k) sm[(s) * P_STG + (m) * 20 + (k)]
#define PBS(s, n, k) sm[(s) * P_STG + 2560 + (n) * 20 + (k)]
#define PCS(n, m)    sm[(n) * 132 + (m)]

__global__ __launch_bounds__(256, 2) void k_proj(
    const float* __restrict__ P, const float* __restrict__ mask,
    const float* __restrict__ Wl, const float* __restrict__ Wr)
{
    __shared__ __align__(16) float sm[2 * P_STG];   // 40 KB
    float* mV = sm + 32 * 132 + 16;                  // mask row (epilogue reuse)

    const int tid = threadIdx.x;
    const int wid = tid >> 5, lane = tid & 31;
    const int wm = wid & 3, wn = wid >> 2;
    const int group = lane >> 2, tid4 = lane & 3;
    const int bid = blockIdx.x;
    const bool isL = (blockIdx.y == 0);
    const float* __restrict__ W = isL ? Wl : Wr;

    int srcBase, srcStride, dmBase;
    if (isL) {
        srcBase = bid * 128;  srcStride = 1;  dmBase = bid * 128;
    } else {
        int j = bid / 3, k0p = (bid % 3) * 128;
        srcBase = k0p * L + j;  srcStride = L;  dmBase = j * L + k0p;
    }

    // LDSM fragment offsets (floats within a stage) — verified pattern (k_tri).
    int aOff[2], bOff[4];
#pragma unroll
    for (int mt = 0; mt < 2; mt++)
        aOff[mt] = (wm * 32 + mt * 16 + (lane & 7) + 8 * ((lane >> 3) & 1)) * 20
                 + 4 * (lane >> 4);
#pragma unroll
    for (int p = 0; p < 4; p++)
        bOff[p] = 2560 + (wn * 64 + p * 16 + (lane & 7) + 8 * (lane >> 4)) * 20
                + 4 * ((lane >> 3) & 1);

    float acc[2][8][4];
#pragma unroll
    for (int mt = 0; mt < 2; mt++)
#pragma unroll
        for (int nt = 0; nt < 8; nt++)
#pragma unroll
            for (int v = 0; v < 4; v++) acc[mt][nt][v] = 0.f;

    const int mld = tid >> 2;          // 0..63; +64 with p
    const int qld = (tid & 3) * 4;     // k offset 0/4/8/12

    float4 va[2], vb[2];
#define P_FETCH(k0)                                                                 \
    {                                                                               \
        _Pragma("unroll")                                                           \
        for (int p = 0; p < 2; p++) {                                               \
            int m = mld + p * 64;                                                   \
            va[p] = *(const float4*)&P[(size_t)(srcBase + (size_t)m * srcStride) * D + (k0) + qld]; \
            vb[p] = *(const float4*)&W[m * D + (k0) + qld];                         \
        }                                                                           \
    }
#define P_STORE(s)                                                                  \
    {                                                                               \
        _Pragma("unroll")                                                           \
        for (int p = 0; p < 2; p++) {                                               \
            int m = mld + p * 64;                                                   \
            PAS(s, m, qld + 0) = f2tff(va[p].x);                                    \
            PAS(s, m, qld + 1) = f2tff(va[p].y);                                    \
            PAS(s, m, qld + 2) = f2tff(va[p].z);                                    \
            PAS(s, m, qld + 3) = f2tff(va[p].w);                                    \
            PBS(s, m, qld + 0) = f2tff(vb[p].x);                                    \
            PBS(s, m, qld + 1) = f2tff(vb[p].y);                                    \
            PBS(s, m, qld + 2) = f2tff(vb[p].z);                                    \
            PBS(s, m, qld + 3) = f2tff(vb[p].w);                                    \
        }                                                                           \
    }

    P_FETCH(0);
    P_STORE(0);
    P_FETCH(16);
    __syncthreads();

#pragma unroll 1
    for (int it = 0; it < 8; it++) {
        const int s = it & 1;
        if (it + 1 < 8) P_STORE(s ^ 1);
#pragma unroll
        for (int ks = 0; ks < 2; ks++) {
            const int k = ks * 8;
            unsigned a[2][4], b[4][4];
#pragma unroll
            for (int mt = 0; mt < 2; mt++)
                ldsm4(a[mt], &sm[s * P_STG + aOff[mt] + k]);
#pragma unroll
            for (int p = 0; p < 4; p++)
                ldsm4(b[p], &sm[s * P_STG + bOff[p] + k]);
#pragma unroll
            for (int mt = 0; mt < 2; mt++)
#pragma unroll
                for (int p = 0; p < 4; p++) {
                    mma8(acc[mt][2 * p],     a[mt], &b[p][0]);
                    mma8(acc[mt][2 * p + 1], a[mt], &b[p][2]);
                }
        }
        if (it + 2 < 8) P_FETCH((it + 2) * 16);
        __syncthreads();
    }
#undef P_FETCH
#undef P_STORE

    if (tid < 128) mV[tid] = mask[dmBase + tid];
    float* __restrict__ dst = isL ? g_LhT : g_RhT;

#pragma unroll 1
    for (int nc = 0; nc < 4; nc++) {
        __syncthreads();
        if (wn == (nc >> 1)) {
#pragma unroll
            for (int nt2 = 0; nt2 < 4; nt2++) {
                int nt = (nc & 1) * 4 + nt2;
                int cc = nt2 * 8 + 2 * tid4;
#pragma unroll
                for (int mt = 0; mt < 2; mt++) {
                    int r = wm * 32 + mt * 16 + group;
                    PCS(cc,     r)     = acc[mt][nt][0];
                    PCS(cc + 1, r)     = acc[mt][nt][1];
                    PCS(cc,     r + 8) = acc[mt][nt][2];
                    PCS(cc + 1, r + 8) = acc[mt][nt][3];
                }
            }
        }
        __syncthreads();
#pragma unroll
        for (int p = 0; p < 4; p++) {
            int nr = (tid >> 5) + p * 8;
            int m  = (tid & 31) * 4;
            float4 o;
            o.x = f2tff(PCS(nr, m + 0) * mV[m + 0]);
            o.y = f2tff(PCS(nr, m + 1) * mV[m + 1]);
            o.z = f2tff(PCS(nr, m + 2) * mV[m + 2]);
            o.w = f2tff(PCS(nr, m + 3) * mV[m + 3]);
            *(float4*)&dst[(size_t)(nc * 32 + nr) * LL + dmBase + m] = o;
        }
    }
#undef PAS
#undef PBS
#undef PCS
}

// ---------------------------------------------------------------------------
// Kernel 2: triangle einsum (tf32 mma + ldmatrix). Unchanged from round 6.
// ---------------------------------------------------------------------------
#define T_STG 5120
#define TAS(s, m, k) sm[(s) * T_STG + (m) * 20 + (k)]
#define TBS(s, n, k) sm[(s) * T_STG + 2560 + (n) * 20 + (k)]
#define TCS(m, j)    sm[(m) * 132 + (j)]

__global__ __launch_bounds__(256, 2) void k_tri() {
    __shared__ __align__(16) float sm[2 * T_STG];   // 40 KB

    const int tid = threadIdx.x;
    const int wid = tid >> 5, lane = tid & 31;
    const int wm = wid & 3, wn = wid >> 2;
    const int group = lane >> 2, tid4 = lane & 3;
    const size_t hoff = (size_t)blockIdx.z * LL;
    const int i0 = blockIdx.y * 128;
    const int j0 = blockIdx.x * 128;

    const float* __restrict__ A = g_LhT + hoff;
    const float* __restrict__ B = g_RhT + hoff;

    int aOff[2], bOff[4];
#pragma unroll
    for (int mt = 0; mt < 2; mt++)
        aOff[mt] = (wm * 32 + mt * 16 + (lane & 7) + 8 * ((lane >> 3) & 1)) * 20
                 + 4 * (lane >> 4);
#pragma unroll
    for (int p = 0; p < 4; p++)
        bOff[p] = 2560 + (wn * 64 + p * 16 + (lane & 7) + 8 * (lane >> 4)) * 20
                + 4 * ((lane >> 3) & 1);

    float acc[2][8][4];
#pragma unroll
    for (int mt = 0; mt < 2; mt++)
#pragma unroll
        for (int nt = 0; nt < 8; nt++)
#pragma unroll
            for (int v = 0; v < 4; v++) acc[mt][nt][v] = 0.f;

#define T_LOAD(s, k0)                                                          \
    {                                                                          \
        _Pragma("unroll")                                                      \
        for (int p = 0; p < 2; p++) {                                          \
            int task = tid + p * 256;                                          \
            int r = task >> 2, q = task & 3;                                   \
            cpa16(&TAS(s, r, q * 4), &A[(size_t)(i0 + r) * L + (k0) + q * 4]); \
            cpa16(&TBS(s, r, q * 4), &B[(size_t)(j0 + r) * L + (k0) + q * 4]); \
        }                                                                      \
    }

    T_LOAD(0, 0);  cpa_commit();
    T_LOAD(1, 16); cpa_commit();

#pragma unroll 2
    for (int it = 0; it < 24; it++) {
        const int s = it & 1;
        cpa_wait1();
        __syncthreads();
#pragma unroll
        for (int ks = 0; ks < 2; ks++) {
            const int k = ks * 8;
            unsigned a[2][4], b[4][4];
#pragma unroll
            for (int mt = 0; mt < 2; mt++)
                ldsm4(a[mt], &sm[s * T_STG + aOff[mt] + k]);
#pragma unroll
            for (int p = 0; p < 4; p++)
                ldsm4(b[p], &sm[s * T_STG + bOff[p] + k]);
#pragma unroll
            for (int mt = 0; mt < 2; mt++)
#pragma unroll
                for (int p = 0; p < 4; p++) {
                    mma8(acc[mt][2 * p],     a[mt], &b[p][0]);
                    mma8(acc[mt][2 * p + 1], a[mt], &b[p][2]);
                }
        }
        __syncthreads();
        if (it + 2 < 24) T_LOAD(s, (it + 2) * 16);
        cpa_commit();
    }

#pragma unroll 1
    for (int mc = 0; mc < 2; mc++) {
        __syncthreads();
        if ((wm >> 1) == mc) {
#pragma unroll
            for (int nt = 0; nt < 8; nt++) {
                int cc = wn * 64 + nt * 8 + 2 * tid4;
#pragma unroll
                for (int mt = 0; mt < 2; mt++) {
                    int r = (wm & 1) * 32 + mt * 16 + group;
                    TCS(r,     cc)     = acc[mt][nt][0];
                    TCS(r,     cc + 1) = acc[mt][nt][1];
                    TCS(r + 8, cc)     = acc[mt][nt][2];
                    TCS(r + 8, cc + 1) = acc[mt][nt][3];
                }
            }
        }
        __syncthreads();
#pragma unroll
        for (int p = 0; p < 8; p++) {
            int row = (tid >> 5) + p * 8;
            int j   = (tid & 31) * 4;
            float4 o;
            o.x = f2tff(TCS(row, j + 0));
            o.y = f2tff(TCS(row, j + 1));
            o.z = f2tff(TCS(row, j + 2));
            o.w = f2tff(TCS(row, j + 3));
            *(float4*)&g_updT[hoff + (size_t)(i0 + mc * 64 + row) * L + j0 + j] = o;
        }
    }
#undef T_LOAD
}
#undef TAS
#undef TBS
#undef TCS

// ---------------------------------------------------------------------------
// Kernel 3: output projection (tf32 mma, B via ldmatrix) + residual + mask + LN.
// A tile [k][m] pitch 136 (scalar frags); B tile [n=d][k=h] pitch 20 (LDSM),
// fed from g_Wo2 native layout. 2-stage cp.async.
// ---------------------------------------------------------------------------
#define F_STG 4736                    // floats: A 16*136 + B 128*20
#define FAS(s, k, m) sm[(s) * F_STG + (k) * 136 + (m)]
#define FBS(s, n, k) sm[(s) * F_STG + 2176 + (n) * 20 + (k)]
#define FCS(m, d)    sm[(m) * 132 + (d)]

__global__ __launch_bounds__(256, 2) void k_fin(
    const float* __restrict__ P, const float* __restrict__ mask,
    const float* __restrict__ gamma, const float* __restrict__ beta,
    float* __restrict__ out)
{
    __shared__ __align__(16) float sm[2 * F_STG];   // 37.9 KB

    const int tid = threadIdx.x;
    const int wid = tid >> 5, lane = tid & 31;
    const int wm = wid & 3, wn = wid >> 2;
    const int group = lane >> 2, tid4 = lane & 3;
    const int pairBase = blockIdx.x * 128;

    int bOff[4];
#pragma unroll
    for (int p = 0; p < 4; p++)
        bOff[p] = 2176 + (wn * 64 + p * 16 + (lane & 7) + 8 * (lane >> 4)) * 20
                + 4 * ((lane >> 3) & 1);

    float acc[2][8][4];
#pragma unroll
    for (int mt = 0; mt < 2; mt++)
#pragma unroll
        for (int nt = 0; nt < 8; nt++)
#pragma unroll
            for (int v = 0; v < 4; v++) acc[mt][nt][v] = 0.f;

#define F_LOAD(s, k0)                                                                \
    {                                                                                \
        _Pragma("unroll")                                                            \
        for (int p = 0; p < 2; p++) {                                                \
            int task = tid + p * 256;                                                \
            int k = task >> 5, m4 = (task & 31) * 4;                                 \
            cpa16(&FAS(s, k, m4), &g_updT[(size_t)((k0) + k) * LL + pairBase + m4]); \
        }                                                                            \
        _Pragma("unroll")                                                            \
        for (int p = 0; p < 2; p++) {                                                \
            int task = tid + p * 256;                                                \
            int n = task >> 2, q = (task & 3) * 4;                                   \
            cpa16(&FBS(s, n, q), &g_Wo2[n * H + (k0) + q]);                          \
        }                                                                            \
    }

    F_LOAD(0, 0);  cpa_commit();
    F_LOAD(1, 16); cpa_commit();

#pragma unroll 1
    for (int it = 0; it < 8; it++) {
        const int s = it & 1;
        cpa_wait1();
        __syncthreads();
#pragma unroll
        for (int ks = 0; ks < 2; ks++) {
            const int k = ks * 8;
            unsigned a[2][4], b[4][4];
#pragma unroll
            for (int mt = 0; mt < 2; mt++) {
                int r = wm * 32 + mt * 16 + group;
                a[mt][0] = __float_as_uint(FAS(s, k + tid4,     r));
                a[mt][1] = __float_as_uint(FAS(s, k + tid4,     r + 8));
                a[mt][2] = __float_as_uint(FAS(s, k + tid4 + 4, r));
                a[mt][3] = __float_as_uint(FAS(s, k + tid4 + 4, r + 8));
            }
#pragma unroll
            for (int p = 0; p < 4; p++)
                ldsm4(b[p], &sm[s * F_STG + bOff[p] + k]);
#pragma unroll
            for (int mt = 0; mt < 2; mt++)
#pragma unroll
                for (int p = 0; p < 4; p++) {
                    mma8(acc[mt][2 * p],     a[mt], &b[p][0]);
                    mma8(acc[mt][2 * p + 1], a[mt], &b[p][2]);
                }
        }
        __syncthreads();
        if (it + 2 < 8) F_LOAD(s, (it + 2) * 16);
        cpa_commit();
    }

    // Epilogue: two 64-pair chunks; stage acc -> smem, then LayerNorm.
#pragma unroll 1
    for (int mc = 0; mc < 2; mc++) {
        __syncthreads();
        if ((wm >> 1) == mc) {
#pragma unroll
            for (int nt = 0; nt < 8; nt++) {
                int cc = wn * 64 + nt * 8 + 2 * tid4;
#pragma unroll
                for (int mt = 0; mt < 2; mt++) {
                    int r = (wm & 1) * 32 + mt * 16 + group;
                    FCS(r,     cc)     = acc[mt][nt][0];
                    FCS(r,     cc + 1) = acc[mt][nt][1];
                    FCS(r + 8, cc)     = acc[mt][nt][2];
                    FCS(r + 8, cc + 1) = acc[mt][nt][3];
                }
            }
        }
        __syncthreads();

        const int row = tid >> 2;
        const int q   = tid & 3;
        const int pair = pairBase + mc * 64 + row;
        const float mk = mask[pair];

        float pn[32];
        float s = 0.f, sq = 0.f;
#pragma unroll
        for (int u = 0; u < 8; u++) {
            float4 pv = *(const float4*)&P[(size_t)pair * D + q * 32 + 4 * u];
            pn[4 * u + 0] = pv.x + mk * FCS(row, q * 32 + 4 * u + 0);
            pn[4 * u + 1] = pv.y + mk * FCS(row, q * 32 + 4 * u + 1);
            pn[4 * u + 2] = pv.z + mk * FCS(row, q * 32 + 4 * u + 2);
            pn[4 * u + 3] = pv.w + mk * FCS(row, q * 32 + 4 * u + 3);
        }
#pragma unroll
        for (int v = 0; v < 32; v++) { s += pn[v]; sq = fmaf(pn[v], pn[v], sq); }
        s  += __shfl_down_sync(0xffffffffu, s,  2, 4);
        s  += __shfl_down_sync(0xffffffffu, s,  1, 4);
        sq += __shfl_down_sync(0xffffffffu, sq, 2, 4);
        sq += __shfl_down_sync(0xffffffffu, sq, 1, 4);
        s  = __shfl_sync(0xffffffffu, s,  0, 4);
        sq = __shfl_sync(0xffffffffu, sq, 0, 4);

        const float mu  = s * (1.f / 128.f);
        const float var = sq * (1.f / 128.f) - mu * mu;
        const float inv = rsqrtf(var + 1e-5f);

#pragma unroll
        for (int u = 0; u < 8; u++) {
            int d = q * 32 + 4 * u;
            float4 gv = *(const float4*)&gamma[d];
            float4 bv = *(const float4*)&beta[d];
            float4 o;
            o.x = (pn[4 * u + 0] - mu) * inv * gv.x + bv.x;
            o.y = (pn[4 * u + 1] - mu) * inv * gv.y + bv.y;
            o.z = (pn[4 * u + 2] - mu) * inv * gv.z + bv.z;
            o.w = (pn[4 * u + 3] - mu) * inv * gv.w + bv.w;
            *(float4*)&out[(size_t)pair * D + d] = o;
        }
    }
#undef F_LOAD
}
#undef FAS
#undef FBS
#undef FCS

// ---------------------------------------------------------------------------
extern "C" void kernel_launch(void* const* d_in, const int* in_sizes, int n_in,
                              void* d_out, int out_size) {
    const float* P     = (const float*)d_in[0];
    const float* mask  = (const float*)d_in[1];
    const float* Wl    = (const float*)d_in[2];
    const float* Wr    = (const float*)d_in[3];
    const float* Wo    = (const float*)d_in[4];
    const float* gamma = (const float*)d_in[5];
    const float* beta  = (const float*)d_in[6];
    float* out = (float*)d_out;

    k_wt<<<64, 256>>>(Wo);
    k_proj<<<dim3(LL / 128, 2), 256>>>(P, mask, Wl, Wr);
    k_tri<<<dim3(L / 128, L / 128, H), 256>>>();
    k_fin<<<LL / 128, 256>>>(P, mask, gamma, beta, out);
}

// round 8
// speedup vs baseline: 1.0537x; 1.0537x over previous
#include <cuda_runtime.h>
#include <cstdint>

#define L  384
#define D  128
#define H  128
#define LL (L * L)   // 147456

// Scratch — static device globals (no cudaMalloc allowed).
__device__ float g_LhT[(size_t)H * LL];   // [h][i*L+k]  (tf32-rounded)
__device__ float g_RhT[(size_t)H * LL];   // [h][j*L+k]  (tf32-rounded, j-major)
__device__ float g_updT[(size_t)H * LL];  // [h][i*L+j]  (tf32-rounded)
__device__ float g_Wo2[D * H];            // [d][h] = tf32(W_out[d][h]) (native order)

// ---------------------------------------------------------------------------
// helpers
// ---------------------------------------------------------------------------
__device__ __forceinline__ unsigned f2tf(float x) {
    unsigned r; asm("cvt.rna.tf32.f32 %0, %1;" : "=r"(r) : "f"(x)); return r;
}
__device__ __forceinline__ float f2tff(float x) { return __uint_as_float(f2tf(x)); }

__device__ __forceinline__ void mma8(float c[4], const unsigned a[4], const unsigned b[2]) {
    asm volatile(
        "mma.sync.aligned.m16n8k8.row.col.f32.tf32.tf32.f32 "
        "{%0,%1,%2,%3}, {%4,%5,%6,%7}, {%8,%9}, {%0,%1,%2,%3};"
        : "+f"(c[0]), "+f"(c[1]), "+f"(c[2]), "+f"(c[3])
        : "r"(a[0]), "r"(a[1]), "r"(a[2]), "r"(a[3]), "r"(b[0]), "r"(b[1]));
}

// ldmatrix.x4 on fp32 data viewed as b16 8x8 matrices (8x4 fp32 tiles).
__device__ __forceinline__ void ldsm4(unsigned r[4], const float* p) {
    unsigned a = (unsigned)__cvta_generic_to_shared(p);
    asm volatile("ldmatrix.sync.aligned.m8n8.x4.shared.b16 {%0,%1,%2,%3}, [%4];"
                 : "=r"(r[0]), "=r"(r[1]), "=r"(r[2]), "=r"(r[3]) : "r"(a));
}

__device__ __forceinline__ void cpa16(void* dst, const void* src) {
    unsigned sa = (unsigned)__cvta_generic_to_shared(dst);
    asm volatile("cp.async.cg.shared.global [%0], [%1], 16;" :: "r"(sa), "l"(src));
}
__device__ __forceinline__ void cpa_commit() { asm volatile("cp.async.commit_group;"); }
__device__ __forceinline__ void cpa_wait1()  { asm volatile("cp.async.wait_group 1;"); }

// ---------------------------------------------------------------------------
// Kernel 0: tf32-round W_out (native [d][h] order) -> g_Wo2
// ---------------------------------------------------------------------------
__global__ __launch_bounds__(256) void k_wt(const float* __restrict__ Wo) {
    int idx = blockIdx.x * 256 + threadIdx.x;   // 16384
    g_Wo2[idx] = f2tff(Wo[idx]);
}

// ---------------------------------------------------------------------------
// Kernel 1: projection GEMM (tf32 mma) — round-6 version (best measured).
//   isL: Lh(i, k=c, h) masked by mask[i*L+c]  -> g_LhT[h][i*L+c]
//   isR: Rh(k, j, h)   masked by mask[j*L+k]  -> g_RhT[h][j*L+k]  (j-major)
// ---------------------------------------------------------------------------
__global__ __launch_bounds__(256) void k_proj(
    const float* __restrict__ P, const float* __restrict__ mask,
    const float* __restrict__ Wl, const float* __restrict__ Wr)
{
    __shared__ __align__(16) float sm[8768];
#define PAS(k, m) sm[(k) * 137 + (m)]
#define PBS(k, n) sm[32 * 137 + (k) * 137 + (n)]
#define PCS(n, m) sm[(n) * 132 + (m)]
    float* mV = sm + 32 * 132 + 16;

    const int tid = threadIdx.x;
    const int wid = tid >> 5, lane = tid & 31;
    const int wm = wid & 3, wn = wid >> 2;
    const int group = lane >> 2, tid4 = lane & 3;
    const int bid = blockIdx.x;
    const bool isL = (blockIdx.y == 0);
    const float* __restrict__ W = isL ? Wl : Wr;

    int srcBase, srcStride, dmBase;
    if (isL) {
        srcBase = bid * 128;  srcStride = 1;  dmBase = bid * 128;
    } else {
        int j = bid / 3, k0p = (bid % 3) * 128;
        srcBase = k0p * L + j;  srcStride = L;  dmBase = j * L + k0p;
    }

    float acc[2][8][4];
#pragma unroll
    for (int mt = 0; mt < 2; mt++)
#pragma unroll
        for (int nt = 0; nt < 8; nt++)
#pragma unroll
            for (int v = 0; v < 4; v++) acc[mt][nt][v] = 0.f;

    const int mld = tid >> 3;
    const int kld = (tid & 7) * 4;

    float4 va[4], vb[4];
#pragma unroll
    for (int p = 0; p < 4; p++) {
        va[p] = *(const float4*)&P[(size_t)(srcBase + (size_t)(mld + p * 32) * srcStride) * D + kld];
        vb[p] = *(const float4*)&W[(mld + p * 32) * D + kld];
    }

#pragma unroll
    for (int it = 0; it < 4; it++) {
        __syncthreads();
#pragma unroll
        for (int p = 0; p < 4; p++) {
            int m = mld + p * 32;
            PAS(kld + 0, m) = f2tff(va[p].x);
            PAS(kld + 1, m) = f2tff(va[p].y);
            PAS(kld + 2, m) = f2tff(va[p].z);
            PAS(kld + 3, m) = f2tff(va[p].w);
            PBS(kld + 0, m) = f2tff(vb[p].x);
            PBS(kld + 1, m) = f2tff(vb[p].y);
            PBS(kld + 2, m) = f2tff(vb[p].z);
            PBS(kld + 3, m) = f2tff(vb[p].w);
        }
        __syncthreads();
        if (it < 3) {
            int k0 = (it + 1) * 32;
#pragma unroll
            for (int p = 0; p < 4; p++) {
                va[p] = *(const float4*)&P[(size_t)(srcBase + (size_t)(mld + p * 32) * srcStride) * D + k0 + kld];
                vb[p] = *(const float4*)&W[(mld + p * 32) * D + k0 + kld];
            }
        }
#pragma unroll
        for (int ks = 0; ks < 4; ks++) {
            int k = ks * 8;
            unsigned a[2][4], b[8][2];
#pragma unroll
            for (int mt = 0; mt < 2; mt++) {
                int r = wm * 32 + mt * 16 + group;
                a[mt][0] = __float_as_uint(PAS(k + tid4, r));
                a[mt][1] = __float_as_uint(PAS(k + tid4, r + 8));
                a[mt][2] = __float_as_uint(PAS(k + tid4 + 4, r));
                a[mt][3] = __float_as_uint(PAS(k + tid4 + 4, r + 8));
            }
#pragma unroll
            for (int nt = 0; nt < 8; nt++) {
                int c = wn * 64 + nt * 8 + group;
                b[nt][0] = __float_as_uint(PBS(k + tid4, c));
                b[nt][1] = __float_as_uint(PBS(k + tid4 + 4, c));
            }
#pragma unroll
            for (int mt = 0; mt < 2; mt++)
#pragma unroll
                for (int nt = 0; nt < 8; nt++)
                    mma8(acc[mt][nt], a[mt], b[nt]);
        }
    }

    __syncthreads();
    if (tid < 128) mV[tid] = mask[dmBase + tid];
    float* __restrict__ dst = isL ? g_LhT : g_RhT;

#pragma unroll
    for (int nc = 0; nc < 4; nc++) {
        __syncthreads();
        if (wn == (nc >> 1)) {
#pragma unroll
            for (int nt2 = 0; nt2 < 4; nt2++) {
                int nt = (nc & 1) * 4 + nt2;
                int cc = nt2 * 8 + 2 * tid4;
#pragma unroll
                for (int mt = 0; mt < 2; mt++) {
                    int r = wm * 32 + mt * 16 + group;
                    PCS(cc,     r)     = acc[mt][nt][0];
                    PCS(cc + 1, r)     = acc[mt][nt][1];
                    PCS(cc,     r + 8) = acc[mt][nt][2];
                    PCS(cc + 1, r + 8) = acc[mt][nt][3];
                }
            }
        }
        __syncthreads();
#pragma unroll
        for (int p = 0; p < 4; p++) {
            int nr = (tid >> 5) + p * 8;
            int m  = (tid & 31) * 4;
            float4 o;
            o.x = f2tff(PCS(nr, m + 0) * mV[m + 0]);
            o.y = f2tff(PCS(nr, m + 1) * mV[m + 1]);
            o.z = f2tff(PCS(nr, m + 2) * mV[m + 2]);
            o.w = f2tff(PCS(nr, m + 3) * mV[m + 3]);
            *(float4*)&dst[(size_t)(nc * 32 + nr) * LL + dmBase + m] = o;
        }
    }
#undef PAS
#undef PBS
#undef PCS
}

// ---------------------------------------------------------------------------
// Kernel 2: triangle einsum (tf32 mma + ldmatrix). Unchanged (committed).
// ---------------------------------------------------------------------------
#define T_STG 5120
#define TAS(s, m, k) sm[(s) * T_STG + (m) * 20 + (k)]
#define TBS(s, n, k) sm[(s) * T_STG + 2560 + (n) * 20 + (k)]
#define TCS(m, j)    sm[(m) * 132 + (j)]

__global__ __launch_bounds__(256, 2) void k_tri() {
    __shared__ __align__(16) float sm[2 * T_STG];   // 40 KB

    const int tid = threadIdx.x;
    const int wid = tid >> 5, lane = tid & 31;
    const int wm = wid & 3, wn = wid >> 2;
    const int group = lane >> 2, tid4 = lane & 3;
    const size_t hoff = (size_t)blockIdx.z * LL;
    const int i0 = blockIdx.y * 128;
    const int j0 = blockIdx.x * 128;

    const float* __restrict__ A = g_LhT + hoff;
    const float* __restrict__ B = g_RhT + hoff;

    int aOff[2], bOff[4];
#pragma unroll
    for (int mt = 0; mt < 2; mt++)
        aOff[mt] = (wm * 32 + mt * 16 + (lane & 7) + 8 * ((lane >> 3) & 1)) * 20
                 + 4 * (lane >> 4);
#pragma unroll
    for (int p = 0; p < 4; p++)
        bOff[p] = 2560 + (wn * 64 + p * 16 + (lane & 7) + 8 * (lane >> 4)) * 20
                + 4 * ((lane >> 3) & 1);

    float acc[2][8][4];
#pragma unroll
    for (int mt = 0; mt < 2; mt++)
#pragma unroll
        for (int nt = 0; nt < 8; nt++)
#pragma unroll
            for (int v = 0; v < 4; v++) acc[mt][nt][v] = 0.f;

#define T_LOAD(s, k0)                                                          \
    {                                                                          \
        _Pragma("unroll")                                                      \
        for (int p = 0; p < 2; p++) {                                          \
            int task = tid + p * 256;                                          \
            int r = task >> 2, q = task & 3;                                   \
            cpa16(&TAS(s, r, q * 4), &A[(size_t)(i0 + r) * L + (k0) + q * 4]); \
            cpa16(&TBS(s, r, q * 4), &B[(size_t)(j0 + r) * L + (k0) + q * 4]); \
        }                                                                      \
    }

    T_LOAD(0, 0);  cpa_commit();
    T_LOAD(1, 16); cpa_commit();

#pragma unroll 2
    for (int it = 0; it < 24; it++) {
        const int s = it & 1;
        cpa_wait1();
        __syncthreads();
#pragma unroll
        for (int ks = 0; ks < 2; ks++) {
            const int k = ks * 8;
            unsigned a[2][4], b[4][4];
#pragma unroll
            for (int mt = 0; mt < 2; mt++)
                ldsm4(a[mt], &sm[s * T_STG + aOff[mt] + k]);
#pragma unroll
            for (int p = 0; p < 4; p++)
                ldsm4(b[p], &sm[s * T_STG + bOff[p] + k]);
#pragma unroll
            for (int mt = 0; mt < 2; mt++)
#pragma unroll
                for (int p = 0; p < 4; p++) {
                    mma8(acc[mt][2 * p],     a[mt], &b[p][0]);
                    mma8(acc[mt][2 * p + 1], a[mt], &b[p][2]);
                }
        }
        __syncthreads();
        if (it + 2 < 24) T_LOAD(s, (it + 2) * 16);
        cpa_commit();
    }

#pragma unroll 1
    for (int mc = 0; mc < 2; mc++) {
        __syncthreads();
        if ((wm >> 1) == mc) {
#pragma unroll
            for (int nt = 0; nt < 8; nt++) {
                int cc = wn * 64 + nt * 8 + 2 * tid4;
#pragma unroll
                for (int mt = 0; mt < 2; mt++) {
                    int r = (wm & 1) * 32 + mt * 16 + group;
                    TCS(r,     cc)     = acc[mt][nt][0];
                    TCS(r,     cc + 1) = acc[mt][nt][1];
                    TCS(r + 8, cc)     = acc[mt][nt][2];
                    TCS(r + 8, cc + 1) = acc[mt][nt][3];
                }
            }
        }
        __syncthreads();
#pragma unroll
        for (int p = 0; p < 8; p++) {
            int row = (tid >> 5) + p * 8;
            int j   = (tid & 31) * 4;
            float4 o;
            o.x = f2tff(TCS(row, j + 0));
            o.y = f2tff(TCS(row, j + 1));
            o.z = f2tff(TCS(row, j + 2));
            o.w = f2tff(TCS(row, j + 3));
            *(float4*)&g_updT[hoff + (size_t)(i0 + mc * 64 + row) * L + j0 + j] = o;
        }
    }
#undef T_LOAD
}
#undef TAS
#undef TBS
#undef TCS

// ---------------------------------------------------------------------------
// Kernel 3: output projection + residual + mask + LayerNorm.
// RESTRUCTURED: 4-warp CTAs (128 threads), tile 64 pairs x 128 d, BK=16,
// 2-stage cp.async. Warp grid 2x2 of 32x64 tiles (fragment math unchanged).
// A tile [k16][m64] pitch 72 (scalar frags, conflict-free); B tile [n=d][k]
// pitch 20 via ldmatrix from g_Wo2. 4 CTAs/SM = 4 independent barrier domains.
// ---------------------------------------------------------------------------
#define F_STG 3712                    // floats: A 16*72 + B 128*20
#define FAS(s, k, m) sm[(s) * F_STG + (k) * 72 + (m)]
#define FBS(s, n, k) sm[(s) * F_STG + 1152 + (n) * 20 + (k)]
#define FCS(m, d)    sm[(m) * 132 + (d)]

__global__ __launch_bounds__(128, 4) void k_fin(
    const float* __restrict__ P, const float* __restrict__ mask,
    const float* __restrict__ gamma, const float* __restrict__ beta,
    float* __restrict__ out)
{
    __shared__ __align__(16) float sm[8448];   // max(2*F_STG=7424, 64*132=8448)

    const int tid = threadIdx.x;
    const int wid = tid >> 5, lane = tid & 31;
    const int wm = wid & 1, wn = wid >> 1;     // 2x2 warp grid
    const int group = lane >> 2, tid4 = lane & 3;
    const int pairBase = blockIdx.x * 64;

    int bOff[4];
#pragma unroll
    for (int p = 0; p < 4; p++)
        bOff[p] = 1152 + (wn * 64 + p * 16 + (lane & 7) + 8 * (lane >> 4)) * 20
                + 4 * ((lane >> 3) & 1);

    float acc[2][8][4];
#pragma unroll
    for (int mt = 0; mt < 2; mt++)
#pragma unroll
        for (int nt = 0; nt < 8; nt++)
#pragma unroll
            for (int v = 0; v < 4; v++) acc[mt][nt][v] = 0.f;

#define F_LOAD(s, k0)                                                                \
    {                                                                                \
        _Pragma("unroll")                                                            \
        for (int p = 0; p < 2; p++) {                                                \
            int task = tid + p * 128;                                                \
            int k = task >> 4, m4 = (task & 15) * 4;                                 \
            cpa16(&FAS(s, k, m4), &g_updT[(size_t)((k0) + k) * LL + pairBase + m4]); \
        }                                                                            \
        _Pragma("unroll")                                                            \
        for (int p = 0; p < 4; p++) {                                                \
            int task = tid + p * 128;                                                \
            int n = task >> 2, q = (task & 3) * 4;                                   \
            cpa16(&FBS(s, n, q), &g_Wo2[n * H + (k0) + q]);                          \
        }                                                                            \
    }

    F_LOAD(0, 0);  cpa_commit();
    F_LOAD(1, 16); cpa_commit();

#pragma unroll 1
    for (int it = 0; it < 8; it++) {
        const int s = it & 1;
        cpa_wait1();
        __syncthreads();
#pragma unroll
        for (int ks = 0; ks < 2; ks++) {
            const int k = ks * 8;
            unsigned a[2][4], b[4][4];
#pragma unroll
            for (int mt = 0; mt < 2; mt++) {
                int r = wm * 32 + mt * 16 + group;
                a[mt][0] = __float_as_uint(FAS(s, k + tid4,     r));
                a[mt][1] = __float_as_uint(FAS(s, k + tid4,     r + 8));
                a[mt][2] = __float_as_uint(FAS(s, k + tid4 + 4, r));
                a[mt][3] = __float_as_uint(FAS(s, k + tid4 + 4, r + 8));
            }
#pragma unroll
            for (int p = 0; p < 4; p++)
                ldsm4(b[p], &sm[s * F_STG + bOff[p] + k]);
#pragma unroll
            for (int mt = 0; mt < 2; mt++)
#pragma unroll
                for (int p = 0; p < 4; p++) {
                    mma8(acc[mt][2 * p],     a[mt], &b[p][0]);
                    mma8(acc[mt][2 * p + 1], a[mt], &b[p][2]);
                }
        }
        __syncthreads();
        if (it + 2 < 8) F_LOAD(s, (it + 2) * 16);
        cpa_commit();
    }

    // Epilogue: stage whole 64x128 acc tile -> smem, then LayerNorm.
    __syncthreads();
#pragma unroll
    for (int nt = 0; nt < 8; nt++) {
        int cc = wn * 64 + nt * 8 + 2 * tid4;
#pragma unroll
        for (int mt = 0; mt < 2; mt++) {
            int r = wm * 32 + mt * 16 + group;
            FCS(r,     cc)     = acc[mt][nt][0];
            FCS(r,     cc + 1) = acc[mt][nt][1];
            FCS(r + 8, cc)     = acc[mt][nt][2];
            FCS(r + 8, cc + 1) = acc[mt][nt][3];
        }
    }
    __syncthreads();

    // LayerNorm: 4 threads per pair-row (32 d each), two passes of 32 rows.
#pragma unroll 1
    for (int h2 = 0; h2 < 2; h2++) {
        const int row = (tid >> 2) + h2 * 32;
        const int q   = tid & 3;
        const int pair = pairBase + row;
        const float mk = mask[pair];

        float pn[32];
        float s = 0.f, sq = 0.f;
#pragma unroll
        for (int u = 0; u < 8; u++) {
            float4 pv = *(const float4*)&P[(size_t)pair * D + q * 32 + 4 * u];
            pn[4 * u + 0] = pv.x + mk * FCS(row, q * 32 + 4 * u + 0);
            pn[4 * u + 1] = pv.y + mk * FCS(row, q * 32 + 4 * u + 1);
            pn[4 * u + 2] = pv.z + mk * FCS(row, q * 32 + 4 * u + 2);
            pn[4 * u + 3] = pv.w + mk * FCS(row, q * 32 + 4 * u + 3);
        }
#pragma unroll
        for (int v = 0; v < 32; v++) { s += pn[v]; sq = fmaf(pn[v], pn[v], sq); }
        s  += __shfl_down_sync(0xffffffffu, s,  2, 4);
        s  += __shfl_down_sync(0xffffffffu, s,  1, 4);
        sq += __shfl_down_sync(0xffffffffu, sq, 2, 4);
        sq += __shfl_down_sync(0xffffffffu, sq, 1, 4);
        s  = __shfl_sync(0xffffffffu, s,  0, 4);
        sq = __shfl_sync(0xffffffffu, sq, 0, 4);

        const float mu  = s * (1.f / 128.f);
        const float var = sq * (1.f / 128.f) - mu * mu;
        const float inv = rsqrtf(var + 1e-5f);

#pragma unroll
        for (int u = 0; u < 8; u++) {
            int d = q * 32 + 4 * u;
            float4 gv = *(const float4*)&gamma[d];
            float4 bv = *(const float4*)&beta[d];
            float4 o;
            o.x = (pn[4 * u + 0] - mu) * inv * gv.x + bv.x;
            o.y = (pn[4 * u + 1] - mu) * inv * gv.y + bv.y;
            o.z = (pn[4 * u + 2] - mu) * inv * gv.z + bv.z;
            o.w = (pn[4 * u + 3] - mu) * inv * gv.w + bv.w;
            *(float4*)&out[(size_t)pair * D + d] = o;
        }
    }
#undef F_LOAD
}
#undef FAS
#undef FBS
#undef FCS

// ---------------------------------------------------------------------------
extern "C" void kernel_launch(void* const* d_in, const int* in_sizes, int n_in,
                              void* d_out, int out_size) {
    const float* P     = (const float*)d_in[0];
    const float* mask  = (const float*)d_in[1];
    const float* Wl    = (const float*)d_in[2];
    const float* Wr    = (const float*)d_in[3];
    const float* Wo    = (const float*)d_in[4];
    const float* gamma = (const float*)d_in[5];
    const float* beta  = (const float*)d_in[6];
    float* out = (float*)d_out;

    k_wt<<<64, 256>>>(Wo);
    k_proj<<<dim3(LL / 128, 2), 256>>>(P, mask, Wl, Wr);
    k_tri<<<dim3(L / 128, L / 128, H), 256>>>();
    k_fin<<<LL / 64, 128>>>(P, mask, gamma, beta, out);
}